// round 15
// baseline (speedup 1.0000x reference)
#include <cuda_runtime.h>
#include <cstdint>

// Problem constants
#define V_SIZE   30522
#define HDIM     768
#define BATCH    64
#define SEQ      512
#define NEW_ROWS 10004
#define N_NODES  10002
#define N_SOFT   8
#define N_EDGES  50000
#define LEAKY    0.2f
#define DEG_CAP  96     // max degree capacity; P(Poisson(5) > 96) ~ 1e-60

// ---------------- scratch (static device arrays; no allocations) ----------------
__device__ __align__(128) float g_af[N_NODES * HDIM];   // compacted aggfeat rows
__device__ __align__(128) float g_ne[N_NODES * HDIM];   // compacted output node rows
__device__ float g_wsrc[HDIM];
__device__ float g_wdst[HDIM];
__device__ float g_ssrc[N_NODES];
__device__ float g_sdst[N_NODES];
__device__ int   g_cnt[N_NODES];           // per-dst degree (zeroed by k_init)
__device__ int   g_esrc[N_NODES * DEG_CAP];// per-dst source buckets
__device__ int   g_nf[N_NODES];            // needed flags
__device__ int   g_slot[N_NODES + 1];      // node -> compacted slot
__device__ int   g_sel[N_NODES];           // slot -> node
__device__ int   g_nsel;
__device__ int   g_x64;
__device__ int   g_e64;

// ---------------- helpers ----------------
__device__ __forceinline__ long long ldidx(const void* p, long long i, int is64) {
    if (is64) return ((const long long*)p)[i];
    return (long long)(((const int*)p)[i]);
}

__device__ __forceinline__ void cpa16(uint32_t saddr, const void* gaddr, bool pred) {
    if (pred)
        asm volatile("cp.async.cg.shared.global [%0], [%1], 16;\n" :: "r"(saddr), "l"(gaddr));
    else
        asm volatile("cp.async.cg.shared.global [%0], [%1], 16, 0;\n" :: "r"(saddr), "l"(gaddr));
}

// ---------------- init: zero counters/flags + dtype detect ----------------
__global__ void k_init(const unsigned* x, const unsigned* ei) {
    int i = blockIdx.x * blockDim.x + threadIdx.x;
    if (i < N_NODES) { g_cnt[i] = 0; g_nf[i] = 0; }
    if (i == 0) {
        unsigned a = 0, b = 0;
        #pragma unroll
        for (int j = 0; j < 8; j++) { a |= x[2 * j + 1]; b |= ei[2 * j + 1]; }
        g_x64 = (a == 0) ? 1 : 0;
        g_e64 = (b == 0) ? 1 : 0;
    }
}

// ---------------- w vectors: w_src = W @ a_src, w_dst = W @ a_dst (fp32) ----------------
__global__ void k_wvec(const float* __restrict__ W,
                       const float* __restrict__ asrc,
                       const float* __restrict__ adst) {
    int k = (blockIdx.x * blockDim.x + threadIdx.x) >> 5;
    int lane = threadIdx.x & 31;
    if (k >= HDIM) return;
    const float* wr = W + (long long)k * HDIM;
    float s1 = 0.f, s2 = 0.f;
    #pragma unroll
    for (int j = 0; j < HDIM / 32; j++) {
        int col = lane + 32 * j;
        float v = wr[col];
        s1 += v * asrc[col];
        s2 += v * adst[col];
    }
    #pragma unroll
    for (int o = 16; o; o >>= 1) {
        s1 += __shfl_xor_sync(0xffffffffu, s1, o);
        s2 += __shfl_xor_sync(0xffffffffu, s2, o);
    }
    if (lane == 0) { g_wsrc[k] = s1; g_wdst[k] = s2; }
}

// ---------------- s_src/s_dst = feat . w_src / w_dst ----------------
__global__ void k_sdots(const float* __restrict__ nw) {
    int w = (blockIdx.x * blockDim.x + threadIdx.x) >> 5;
    int lane = threadIdx.x & 31;
    if (w >= N_NODES) return;
    const float* fr = nw + (long long)(1 + w) * HDIM;
    float s1 = 0.f, s2 = 0.f;
    #pragma unroll
    for (int j = 0; j < HDIM / 32; j++) {
        int col = lane + 32 * j;
        float v = fr[col];
        s1 += v * g_wsrc[col];
        s2 += v * g_wdst[col];
    }
    #pragma unroll
    for (int o = 16; o; o >>= 1) {
        s1 += __shfl_xor_sync(0xffffffffu, s1, o);
        s2 += __shfl_xor_sync(0xffffffffu, s2, o);
    }
    if (lane == 0) { g_ssrc[w] = s1; g_sdst[w] = s2; }
}

// ---------------- flags: mark nodes referenced by x ----------------
__global__ void k_flags(const void* __restrict__ x) {
    int i = blockIdx.x * blockDim.x + threadIdx.x;
    if (i >= BATCH * SEQ) return;
    int s = i % SEQ;
    if (s < N_SOFT) return;
    long long idx = ldidx(x, i, g_x64);
    if (idx >= V_SIZE && idx < V_SIZE + N_NODES) g_nf[idx - V_SIZE] = 1;
}

// ---------------- compaction scan: g_nf -> g_slot (exclusive), g_sel, g_nsel ----------------
#define SCAN_NPT 10

__global__ __launch_bounds__(1024) void k_cscan() {
    __shared__ int sv[N_NODES];
    __shared__ int wsum[32];
    int tid = threadIdx.x;
    int lane = tid & 31, warp = tid >> 5;

    for (int i = tid; i < N_NODES; i += 1024) sv[i] = g_nf[i];
    __syncthreads();

    int base = tid * SCAN_NPT;
    int local[SCAN_NPT];
    int tot = 0;
    #pragma unroll
    for (int j = 0; j < SCAN_NPT; j++) {
        int i = base + j;
        int v = (i < N_NODES) ? sv[i] : 0;
        local[j] = tot;
        tot += v;
    }
    int s = tot;
    #pragma unroll
    for (int off = 1; off < 32; off <<= 1) {
        int tv = __shfl_up_sync(0xffffffffu, s, off);
        if (lane >= off) s += tv;
    }
    if (lane == 31) wsum[warp] = s;
    __syncthreads();
    if (warp == 0) {
        int w = wsum[lane];
        #pragma unroll
        for (int off = 1; off < 32; off <<= 1) {
            int tv = __shfl_up_sync(0xffffffffu, w, off);
            if (lane >= off) w += tv;
        }
        wsum[lane] = w;
    }
    __syncthreads();
    int offset = ((warp > 0) ? wsum[warp - 1] : 0) + s - tot;

    #pragma unroll
    for (int j = 0; j < SCAN_NPT; j++) {
        int i = base + j;
        if (i < N_NODES) {
            int p = offset + local[j];
            g_slot[i] = p;
            if (sv[i]) g_sel[p] = i;
        }
    }
    if (tid == 1023) { g_slot[N_NODES] = offset + tot; g_nsel = offset + tot; }
}

// ---------------- edge bucket scatter (replaces hist+scan+scatter) ----------------
__global__ void k_escatter(const void* ei) {
    int e = blockIdx.x * blockDim.x + threadIdx.x;
    if (e < N_EDGES) {
        int src = (int)ldidx(ei, e, g_e64);
        int dst = (int)ldidx(ei, (long long)N_EDGES + e, g_e64);
        int pos = atomicAdd(&g_cnt[dst], 1);
        if (pos < DEG_CAP) g_esrc[dst * DEG_CAP + pos] = src;
    }
}

// ---------------- per-needed-dst softmax + feat-space aggregation (single pass) ----------------
__global__ void k_gat(const float* __restrict__ nw) {
    int w = (blockIdx.x * blockDim.x + threadIdx.x) >> 5;
    int lane = threadIdx.x & 31;
    if (w >= N_NODES) return;
    int slot = g_slot[w];
    if (g_slot[w + 1] <= slot) return;     // node not referenced by x

    int deg = g_cnt[w];
    if (deg > DEG_CAP) deg = DEG_CAP;
    const int* bucket = g_esrc + w * DEG_CAP;
    float sd = g_sdst[w];

    float acc[HDIM / 32];
    #pragma unroll
    for (int cidx = 0; cidx < HDIM / 32; cidx++) acc[cidx] = 0.f;
    float den = 0.f;

    for (int i = 0; i < deg; i++) {
        int s = bucket[i];
        float e = g_ssrc[s] + sd;
        e = (e >= 0.f) ? e : LEAKY * e;
        float wgt = expf(e);               // no max shift needed (|e| << 1)
        den += wgt;
        const float* fr = nw + (long long)(1 + s) * HDIM;
        #pragma unroll
        for (int cidx = 0; cidx < HDIM / 32; cidx++)
            acc[cidx] += wgt * fr[lane + 32 * cidx];
    }

    float inv = 1.0f / (den + 1e-16f);
    float* outr = g_af + (long long)slot * HDIM;
    #pragma unroll
    for (int cidx = 0; cidx < HDIM / 32; cidx++)
        outr[lane + 32 * cidx] = acc[cidx] * inv;
}

// ---------------- GEMM: g_ne[slot] = feat[sel[slot]] + g_af[slot] @ W  (TF32 MMA) ----------------
#define BM 128
#define BN 128
#define BKK 32
#define AS_STRIDE 36
#define BS_STRIDE 136
#define STAGE_FLOATS (BM * AS_STRIDE + BKK * BS_STRIDE)
#define NSTAGE 3
#define GEMM_SMEM_BYTES (NSTAGE * STAGE_FLOATS * 4)

extern __shared__ float dynsmem[];

__global__ __launch_bounds__(256) void k_gemm(const float* __restrict__ W,
                                              const float* __restrict__ nw) {
    const int nsel = g_nsel;
    const int m0 = blockIdx.x * BM;
    if (m0 >= nsel) return;
    const int n0 = blockIdx.y * BN;

    const int tid  = threadIdx.x;
    const int warp = tid >> 5, lane = tid & 31;
    const int wm = warp >> 1, wn = warp & 1;
    const int g = lane >> 2, t = lane & 3;

    float c[2][8][4];
    #pragma unroll
    for (int mm = 0; mm < 2; mm++)
        #pragma unroll
        for (int nn = 0; nn < 8; nn++)
            #pragma unroll
            for (int q = 0; q < 4; q++) c[mm][nn][q] = 0.0f;

    const int NT = HDIM / BKK;   // 24

    auto load_tile = [&](int kt, int stage) {
        float* As = dynsmem + stage * STAGE_FLOATS;
        float* Bs = As + BM * AS_STRIDE;
        #pragma unroll
        for (int i = 0; i < 4; i++) {
            int idx = tid + i * 256;
            int r  = idx >> 3;
            int c4 = (idx & 7) * 4;
            int grow = m0 + r;
            bool ok = grow < nsel;
            const float* gp = g_af + (long long)(ok ? grow : 0) * HDIM + kt + c4;
            uint32_t sa = (uint32_t)__cvta_generic_to_shared(As + r * AS_STRIDE + c4);
            cpa16(sa, gp, ok);
            int k  = idx >> 5;
            int n4 = (idx & 31) * 4;
            const float* gq = W + (long long)(kt + k) * HDIM + n0 + n4;
            uint32_t sb = (uint32_t)__cvta_generic_to_shared(Bs + k * BS_STRIDE + n4);
            cpa16(sb, gq, true);
        }
    };

    load_tile(0, 0);
    asm volatile("cp.async.commit_group;\n");
    load_tile(BKK, 1);
    asm volatile("cp.async.commit_group;\n");

    for (int kt = 0; kt < NT; kt++) {
        if (kt + 2 < NT) {
            int st = kt + 2;
            load_tile(st * BKK, st % NSTAGE);
            asm volatile("cp.async.commit_group;\n");
            asm volatile("cp.async.wait_group 2;\n");
        } else if (kt + 1 < NT) {
            asm volatile("cp.async.wait_group 1;\n");
        } else {
            asm volatile("cp.async.wait_group 0;\n");
        }
        __syncthreads();

        const float* As = dynsmem + (kt % NSTAGE) * STAGE_FLOATS;
        const float* Bs = As + BM * AS_STRIDE;

        #pragma unroll
        for (int ks = 0; ks < 4; ks++) {
            const int kb = ks * 8;
            unsigned a[2][4], b2[8][2];
            #pragma unroll
            for (int mm = 0; mm < 2; mm++) {
                int rb = wm * 32 + mm * 16;
                a[mm][0] = __float_as_uint(As[(rb + g) * AS_STRIDE + kb + t]);
                a[mm][1] = __float_as_uint(As[(rb + 8 + g) * AS_STRIDE + kb + t]);
                a[mm][2] = __float_as_uint(As[(rb + g) * AS_STRIDE + kb + t + 4]);
                a[mm][3] = __float_as_uint(As[(rb + 8 + g) * AS_STRIDE + kb + t + 4]);
            }
            #pragma unroll
            for (int nn = 0; nn < 8; nn++) {
                int col = wn * 64 + nn * 8 + g;
                b2[nn][0] = __float_as_uint(Bs[(kb + t) * BS_STRIDE + col]);
                b2[nn][1] = __float_as_uint(Bs[(kb + t + 4) * BS_STRIDE + col]);
            }
            #pragma unroll
            for (int mm = 0; mm < 2; mm++)
                #pragma unroll
                for (int nn = 0; nn < 8; nn++) {
                    asm volatile(
                        "mma.sync.aligned.m16n8k8.row.col.f32.tf32.tf32.f32 "
                        "{%0,%1,%2,%3},{%4,%5,%6,%7},{%8,%9},{%0,%1,%2,%3};"
                        : "+f"(c[mm][nn][0]), "+f"(c[mm][nn][1]),
                          "+f"(c[mm][nn][2]), "+f"(c[mm][nn][3])
                        : "r"(a[mm][0]), "r"(a[mm][1]), "r"(a[mm][2]), "r"(a[mm][3]),
                          "r"(b2[nn][0]), "r"(b2[nn][1]));
                }
        }
        __syncthreads();
    }

    // Epilogue: g_ne[row] = c + feat[sel[row]]
    #pragma unroll
    for (int mm = 0; mm < 2; mm++) {
        int row = m0 + wm * 32 + mm * 16 + g;
        int nodeA = (row < nsel) ? g_sel[row] : 0;
        int nodeB = (row + 8 < nsel) ? g_sel[row + 8] : 0;
        const float* fA = nw + (long long)(1 + nodeA) * HDIM;
        const float* fB = nw + (long long)(1 + nodeB) * HDIM;
        #pragma unroll
        for (int nn = 0; nn < 8; nn++) {
            int col = n0 + wn * 64 + nn * 8 + t * 2;
            if (row < nsel) {
                float2 fv = *(const float2*)(fA + col);
                float2 v0 = make_float2(c[mm][nn][0] + fv.x, c[mm][nn][1] + fv.y);
                *(float2*)(g_ne + (long long)row * HDIM + col) = v0;
            }
            if (row + 8 < nsel) {
                float2 fv = *(const float2*)(fB + col);
                float2 v1 = make_float2(c[mm][nn][2] + fv.x, c[mm][nn][3] + fv.y);
                *(float2*)(g_ne + (long long)(row + 8) * HDIM + col) = v1;
            }
        }
    }
}

// ---------------- gather (static rows): soft prompt + original vocab + tail ----------------
__global__ void k_gather_static(const void* __restrict__ x,
                                const float* __restrict__ ow,
                                const float* __restrict__ nw,
                                const float* __restrict__ soft,
                                float* __restrict__ out) {
    int w = (blockIdx.x * blockDim.x + threadIdx.x) >> 5;
    int lane = threadIdx.x & 31;
    if (w >= BATCH * SEQ) return;
    int b = w / SEQ, s = w % SEQ;

    const float* srcrow;
    if (s < N_SOFT) {
        srcrow = soft + (long long)s * HDIM;
    } else {
        long long idx = ldidx(x, (long long)b * SEQ + s, g_x64);
        if (idx < V_SIZE)                      srcrow = ow + idx * HDIM;
        else if (idx >= V_SIZE + N_NODES)      srcrow = nw + (long long)(NEW_ROWS - 1) * HDIM;
        else return;
    }
    const float4* s4 = (const float4*)srcrow;
    float4* o4 = (float4*)(out + (long long)w * HDIM);
    #pragma unroll
    for (int j = 0; j < HDIM / 128; j++)
        o4[lane + 32 * j] = s4[lane + 32 * j];
}

// ---------------- gather (dynamic rows): compacted GAT-updated node embeddings ----------------
__global__ void k_gather_dyn(const void* __restrict__ x,
                             float* __restrict__ out) {
    int w = (blockIdx.x * blockDim.x + threadIdx.x) >> 5;
    int lane = threadIdx.x & 31;
    if (w >= BATCH * SEQ) return;
    int b = w / SEQ, s = w % SEQ;
    if (s < N_SOFT) return;

    long long idx = ldidx(x, (long long)b * SEQ + s, g_x64);
    if (idx < V_SIZE || idx >= V_SIZE + N_NODES) return;

    int slot = g_slot[idx - V_SIZE];
    const float4* s4 = (const float4*)(g_ne + (long long)slot * HDIM);
    float4* o4 = (float4*)(out + (long long)w * HDIM);
    #pragma unroll
    for (int j = 0; j < HDIM / 128; j++)
        o4[lane + 32 * j] = s4[lane + 32 * j];
}

// ---------------- launch ----------------
extern "C" void kernel_launch(void* const* d_in, const int* in_sizes, int n_in,
                              void* d_out, int out_size) {
    const void*  x    = d_in[0];
    const void*  ei   = d_in[1];
    const float* ow   = (const float*)d_in[2];
    const float* nw   = (const float*)d_in[3];
    const float* soft = (const float*)d_in[4];
    const float* Wg   = (const float*)d_in[5];
    const float* asrc = (const float*)d_in[6];
    const float* adst = (const float*)d_in[7];
    float* out = (float*)d_out;

    static cudaStream_t s_csr = nullptr, s_emb = nullptr, s_wv = nullptr;
    static cudaEvent_t  e_init = nullptr, e_csr = nullptr, e_emb = nullptr, e_sd = nullptr;
    if (!s_csr) {
        cudaFuncSetAttribute(k_gemm, cudaFuncAttributeMaxDynamicSharedMemorySize,
                             GEMM_SMEM_BYTES);
        cudaStreamCreateWithFlags(&s_csr, cudaStreamNonBlocking);
        cudaStreamCreateWithFlags(&s_emb, cudaStreamNonBlocking);
        cudaStreamCreateWithFlags(&s_wv,  cudaStreamNonBlocking);
        cudaEventCreateWithFlags(&e_init, cudaEventDisableTiming);
        cudaEventCreateWithFlags(&e_csr,  cudaEventDisableTiming);
        cudaEventCreateWithFlags(&e_emb,  cudaEventDisableTiming);
        cudaEventCreateWithFlags(&e_sd,   cudaEventDisableTiming);
    }

    // main stream: init (zero + dtype detect)
    k_init<<<(N_NODES + 1023) / 1024, 1024>>>((const unsigned*)x, (const unsigned*)ei);
    cudaEventRecord(e_init, 0);

    // s_wv: fork from capture-origin stream via event, then score chain
    cudaStreamWaitEvent(s_wv, e_init, 0);
    k_wvec<<<(HDIM * 32 + 255) / 256, 256, 0, s_wv>>>(Wg, asrc, adst);
    k_sdots<<<(N_NODES * 32 + 255) / 256, 256, 0, s_wv>>>(nw);
    cudaEventRecord(e_sd, s_wv);

    // s_csr: single bucket-scatter kernel (replaces hist -> scan -> scatter)
    cudaStreamWaitEvent(s_csr, e_init, 0);
    k_escatter<<<(N_EDGES + 1023) / 1024, 1024, 0, s_csr>>>(ei);
    cudaEventRecord(e_csr, s_csr);

    // s_emb: static gather
    cudaStreamWaitEvent(s_emb, e_init, 0);
    k_gather_static<<<(BATCH * SEQ * 32 + 255) / 256, 256, 0, s_emb>>>(x, ow, nw, soft, out);
    cudaEventRecord(e_emb, s_emb);

    // main stream: flags -> compaction scan
    k_flags<<<(BATCH * SEQ + 255) / 256, 256>>>(x);
    k_cscan<<<1, 1024>>>();

    // join bucket scatter + sdots, run feat-space GAT aggregation (single-pass softmax)
    cudaStreamWaitEvent(0, e_csr, 0);
    cudaStreamWaitEvent(0, e_sd, 0);
    k_gat<<<(N_NODES * 32 + 255) / 256, 256>>>(nw);

    // compacted GEMM (agg @ W + feat)
    dim3 ggrid((N_NODES + BM - 1) / BM, HDIM / BN);
    k_gemm<<<ggrid, 256, GEMM_SMEM_BYTES>>>(Wg, nw);

    // dynamic gather
    cudaStreamWaitEvent(0, e_emb, 0);
    k_gather_dyn<<<(BATCH * SEQ * 32 + 255) / 256, 256>>>(x, out);
}

// round 16
// speedup vs baseline: 1.0776x; 1.0776x over previous
#include <cuda_runtime.h>
#include <cstdint>

// Problem constants
#define V_SIZE   30522
#define HDIM     768
#define BATCH    64
#define SEQ      512
#define NEW_ROWS 10004
#define N_NODES  10002
#define N_SOFT   8
#define N_EDGES  50000
#define LEAKY    0.2f
#define DEG_CAP  96     // max degree capacity; P(Poisson(5) > 96) ~ 1e-60

// ---------------- scratch (static device arrays; no allocations) ----------------
__device__ __align__(128) float g_af[N_NODES * HDIM];   // compacted aggfeat rows
__device__ __align__(128) float g_ne[N_NODES * HDIM];   // compacted output node rows
__device__ float g_wsrc[HDIM];
__device__ float g_wdst[HDIM];
__device__ float g_ssrc[N_NODES];
__device__ float g_sdst[N_NODES];
__device__ int   g_cnt[N_NODES];           // per-dst degree (zeroed by k_init)
__device__ int   g_esrc[N_NODES * DEG_CAP];// per-dst source buckets
__device__ int   g_nf[N_NODES];            // needed flags (zeroed by k_init)
__device__ int   g_slot[N_NODES];          // node -> compacted slot (atomic-assigned)
__device__ int   g_sel[N_NODES];           // slot -> node
__device__ int   g_nsel;                   // zeroed by k_init
__device__ int   g_x64;
__device__ int   g_e64;

// ---------------- helpers ----------------
__device__ __forceinline__ long long ldidx(const void* p, long long i, int is64) {
    if (is64) return ((const long long*)p)[i];
    return (long long)(((const int*)p)[i]);
}

__device__ __forceinline__ void cpa16(uint32_t saddr, const void* gaddr, bool pred) {
    if (pred)
        asm volatile("cp.async.cg.shared.global [%0], [%1], 16;\n" :: "r"(saddr), "l"(gaddr));
    else
        asm volatile("cp.async.cg.shared.global [%0], [%1], 16, 0;\n" :: "r"(saddr), "l"(gaddr));
}

// ---------------- init: zero counters/flags/nsel + dtype detect ----------------
__global__ void k_init(const unsigned* x, const unsigned* ei) {
    int i = blockIdx.x * blockDim.x + threadIdx.x;
    if (i < N_NODES) { g_cnt[i] = 0; g_nf[i] = 0; }
    if (i == 0) {
        g_nsel = 0;
        unsigned a = 0, b = 0;
        #pragma unroll
        for (int j = 0; j < 8; j++) { a |= x[2 * j + 1]; b |= ei[2 * j + 1]; }
        g_x64 = (a == 0) ? 1 : 0;
        g_e64 = (b == 0) ? 1 : 0;
    }
}

// ---------------- w vectors: w_src = W @ a_src, w_dst = W @ a_dst (fp32) ----------------
__global__ void k_wvec(const float* __restrict__ W,
                       const float* __restrict__ asrc,
                       const float* __restrict__ adst) {
    int k = (blockIdx.x * blockDim.x + threadIdx.x) >> 5;
    int lane = threadIdx.x & 31;
    if (k >= HDIM) return;
    const float* wr = W + (long long)k * HDIM;
    float s1 = 0.f, s2 = 0.f;
    #pragma unroll
    for (int j = 0; j < HDIM / 32; j++) {
        int col = lane + 32 * j;
        float v = wr[col];
        s1 += v * asrc[col];
        s2 += v * adst[col];
    }
    #pragma unroll
    for (int o = 16; o; o >>= 1) {
        s1 += __shfl_xor_sync(0xffffffffu, s1, o);
        s2 += __shfl_xor_sync(0xffffffffu, s2, o);
    }
    if (lane == 0) { g_wsrc[k] = s1; g_wdst[k] = s2; }
}

// ---------------- s_src/s_dst = feat . w_src / w_dst ----------------
__global__ void k_sdots(const float* __restrict__ nw) {
    int w = (blockIdx.x * blockDim.x + threadIdx.x) >> 5;
    int lane = threadIdx.x & 31;
    if (w >= N_NODES) return;
    const float* fr = nw + (long long)(1 + w) * HDIM;
    float s1 = 0.f, s2 = 0.f;
    #pragma unroll
    for (int j = 0; j < HDIM / 32; j++) {
        int col = lane + 32 * j;
        float v = fr[col];
        s1 += v * g_wsrc[col];
        s2 += v * g_wdst[col];
    }
    #pragma unroll
    for (int o = 16; o; o >>= 1) {
        s1 += __shfl_xor_sync(0xffffffffu, s1, o);
        s2 += __shfl_xor_sync(0xffffffffu, s2, o);
    }
    if (lane == 0) { g_ssrc[w] = s1; g_sdst[w] = s2; }
}

// ---------------- flag + atomic slot assignment (replaces flags + cscan) ----------------
// Slot order is run-dependent, but every consumer dereferences through g_slot[node],
// so the final output bytes are identical regardless of the permutation.
__global__ void k_flagslot(const void* __restrict__ x) {
    int i = blockIdx.x * blockDim.x + threadIdx.x;
    if (i >= BATCH * SEQ) return;
    int s = i % SEQ;
    if (s < N_SOFT) return;
    long long idx = ldidx(x, i, g_x64);
    if (idx >= V_SIZE && idx < V_SIZE + N_NODES) {
        int node = (int)(idx - V_SIZE);
        if (atomicCAS(&g_nf[node], 0, 1) == 0) {
            int p = atomicAdd(&g_nsel, 1);
            g_slot[node] = p;
            g_sel[p] = node;
        }
    }
}

// ---------------- edge bucket scatter ----------------
__global__ void k_escatter(const void* ei) {
    int e = blockIdx.x * blockDim.x + threadIdx.x;
    if (e < N_EDGES) {
        int src = (int)ldidx(ei, e, g_e64);
        int dst = (int)ldidx(ei, (long long)N_EDGES + e, g_e64);
        int pos = atomicAdd(&g_cnt[dst], 1);
        if (pos < DEG_CAP) g_esrc[dst * DEG_CAP + pos] = src;
    }
}

// ---------------- per-needed-dst softmax + feat-space aggregation (single pass) ----------------
__global__ void k_gat(const float* __restrict__ nw) {
    int w = (blockIdx.x * blockDim.x + threadIdx.x) >> 5;
    int lane = threadIdx.x & 31;
    if (w >= N_NODES) return;
    if (!g_nf[w]) return;                  // node not referenced by x
    int slot = g_slot[w];

    int deg = g_cnt[w];
    if (deg > DEG_CAP) deg = DEG_CAP;
    const int* bucket = g_esrc + w * DEG_CAP;
    float sd = g_sdst[w];

    float acc[HDIM / 32];
    #pragma unroll
    for (int cidx = 0; cidx < HDIM / 32; cidx++) acc[cidx] = 0.f;
    float den = 0.f;

    for (int i = 0; i < deg; i++) {
        int s = bucket[i];
        float e = g_ssrc[s] + sd;
        e = (e >= 0.f) ? e : LEAKY * e;
        float wgt = expf(e);               // no max shift needed (|e| << 1)
        den += wgt;
        const float* fr = nw + (long long)(1 + s) * HDIM;
        #pragma unroll
        for (int cidx = 0; cidx < HDIM / 32; cidx++)
            acc[cidx] += wgt * fr[lane + 32 * cidx];
    }

    float inv = 1.0f / (den + 1e-16f);
    float* outr = g_af + (long long)slot * HDIM;
    #pragma unroll
    for (int cidx = 0; cidx < HDIM / 32; cidx++)
        outr[lane + 32 * cidx] = acc[cidx] * inv;
}

// ---------------- GEMM: g_ne[slot] = feat[sel[slot]] + g_af[slot] @ W  (TF32 MMA) ----------------
#define BM 128
#define BN 128
#define BKK 32
#define AS_STRIDE 36
#define BS_STRIDE 136
#define STAGE_FLOATS (BM * AS_STRIDE + BKK * BS_STRIDE)
#define NSTAGE 3
#define GEMM_SMEM_BYTES (NSTAGE * STAGE_FLOATS * 4)

extern __shared__ float dynsmem[];

__global__ __launch_bounds__(256) void k_gemm(const float* __restrict__ W,
                                              const float* __restrict__ nw) {
    const int nsel = g_nsel;
    const int m0 = blockIdx.x * BM;
    if (m0 >= nsel) return;
    const int n0 = blockIdx.y * BN;

    const int tid  = threadIdx.x;
    const int warp = tid >> 5, lane = tid & 31;
    const int wm = warp >> 1, wn = warp & 1;
    const int g = lane >> 2, t = lane & 3;

    float c[2][8][4];
    #pragma unroll
    for (int mm = 0; mm < 2; mm++)
        #pragma unroll
        for (int nn = 0; nn < 8; nn++)
            #pragma unroll
            for (int q = 0; q < 4; q++) c[mm][nn][q] = 0.0f;

    const int NT = HDIM / BKK;   // 24

    auto load_tile = [&](int kt, int stage) {
        float* As = dynsmem + stage * STAGE_FLOATS;
        float* Bs = As + BM * AS_STRIDE;
        #pragma unroll
        for (int i = 0; i < 4; i++) {
            int idx = tid + i * 256;
            int r  = idx >> 3;
            int c4 = (idx & 7) * 4;
            int grow = m0 + r;
            bool ok = grow < nsel;
            const float* gp = g_af + (long long)(ok ? grow : 0) * HDIM + kt + c4;
            uint32_t sa = (uint32_t)__cvta_generic_to_shared(As + r * AS_STRIDE + c4);
            cpa16(sa, gp, ok);
            int k  = idx >> 5;
            int n4 = (idx & 31) * 4;
            const float* gq = W + (long long)(kt + k) * HDIM + n0 + n4;
            uint32_t sb = (uint32_t)__cvta_generic_to_shared(Bs + k * BS_STRIDE + n4);
            cpa16(sb, gq, true);
        }
    };

    load_tile(0, 0);
    asm volatile("cp.async.commit_group;\n");
    load_tile(BKK, 1);
    asm volatile("cp.async.commit_group;\n");

    for (int kt = 0; kt < NT; kt++) {
        if (kt + 2 < NT) {
            int st = kt + 2;
            load_tile(st * BKK, st % NSTAGE);
            asm volatile("cp.async.commit_group;\n");
            asm volatile("cp.async.wait_group 2;\n");
        } else if (kt + 1 < NT) {
            asm volatile("cp.async.wait_group 1;\n");
        } else {
            asm volatile("cp.async.wait_group 0;\n");
        }
        __syncthreads();

        const float* As = dynsmem + (kt % NSTAGE) * STAGE_FLOATS;
        const float* Bs = As + BM * AS_STRIDE;

        #pragma unroll
        for (int ks = 0; ks < 4; ks++) {
            const int kb = ks * 8;
            unsigned a[2][4], b2[8][2];
            #pragma unroll
            for (int mm = 0; mm < 2; mm++) {
                int rb = wm * 32 + mm * 16;
                a[mm][0] = __float_as_uint(As[(rb + g) * AS_STRIDE + kb + t]);
                a[mm][1] = __float_as_uint(As[(rb + 8 + g) * AS_STRIDE + kb + t]);
                a[mm][2] = __float_as_uint(As[(rb + g) * AS_STRIDE + kb + t + 4]);
                a[mm][3] = __float_as_uint(As[(rb + 8 + g) * AS_STRIDE + kb + t + 4]);
            }
            #pragma unroll
            for (int nn = 0; nn < 8; nn++) {
                int col = wn * 64 + nn * 8 + g;
                b2[nn][0] = __float_as_uint(Bs[(kb + t) * BS_STRIDE + col]);
                b2[nn][1] = __float_as_uint(Bs[(kb + t + 4) * BS_STRIDE + col]);
            }
            #pragma unroll
            for (int mm = 0; mm < 2; mm++)
                #pragma unroll
                for (int nn = 0; nn < 8; nn++) {
                    asm volatile(
                        "mma.sync.aligned.m16n8k8.row.col.f32.tf32.tf32.f32 "
                        "{%0,%1,%2,%3},{%4,%5,%6,%7},{%8,%9},{%0,%1,%2,%3};"
                        : "+f"(c[mm][nn][0]), "+f"(c[mm][nn][1]),
                          "+f"(c[mm][nn][2]), "+f"(c[mm][nn][3])
                        : "r"(a[mm][0]), "r"(a[mm][1]), "r"(a[mm][2]), "r"(a[mm][3]),
                          "r"(b2[nn][0]), "r"(b2[nn][1]));
                }
        }
        __syncthreads();
    }

    // Epilogue: g_ne[row] = c + feat[sel[row]]
    #pragma unroll
    for (int mm = 0; mm < 2; mm++) {
        int row = m0 + wm * 32 + mm * 16 + g;
        int nodeA = (row < nsel) ? g_sel[row] : 0;
        int nodeB = (row + 8 < nsel) ? g_sel[row + 8] : 0;
        const float* fA = nw + (long long)(1 + nodeA) * HDIM;
        const float* fB = nw + (long long)(1 + nodeB) * HDIM;
        #pragma unroll
        for (int nn = 0; nn < 8; nn++) {
            int col = n0 + wn * 64 + nn * 8 + t * 2;
            if (row < nsel) {
                float2 fv = *(const float2*)(fA + col);
                float2 v0 = make_float2(c[mm][nn][0] + fv.x, c[mm][nn][1] + fv.y);
                *(float2*)(g_ne + (long long)row * HDIM + col) = v0;
            }
            if (row + 8 < nsel) {
                float2 fv = *(const float2*)(fB + col);
                float2 v1 = make_float2(c[mm][nn][2] + fv.x, c[mm][nn][3] + fv.y);
                *(float2*)(g_ne + (long long)(row + 8) * HDIM + col) = v1;
            }
        }
    }
}

// ---------------- gather (static rows): soft prompt + original vocab + tail ----------------
__global__ void k_gather_static(const void* __restrict__ x,
                                const float* __restrict__ ow,
                                const float* __restrict__ nw,
                                const float* __restrict__ soft,
                                float* __restrict__ out) {
    int w = (blockIdx.x * blockDim.x + threadIdx.x) >> 5;
    int lane = threadIdx.x & 31;
    if (w >= BATCH * SEQ) return;
    int b = w / SEQ, s = w % SEQ;

    const float* srcrow;
    if (s < N_SOFT) {
        srcrow = soft + (long long)s * HDIM;
    } else {
        long long idx = ldidx(x, (long long)b * SEQ + s, g_x64);
        if (idx < V_SIZE)                      srcrow = ow + idx * HDIM;
        else if (idx >= V_SIZE + N_NODES)      srcrow = nw + (long long)(NEW_ROWS - 1) * HDIM;
        else return;
    }
    const float4* s4 = (const float4*)srcrow;
    float4* o4 = (float4*)(out + (long long)w * HDIM);
    #pragma unroll
    for (int j = 0; j < HDIM / 128; j++)
        o4[lane + 32 * j] = s4[lane + 32 * j];
}

// ---------------- gather (dynamic rows): compacted GAT-updated node embeddings ----------------
__global__ void k_gather_dyn(const void* __restrict__ x,
                             float* __restrict__ out) {
    int w = (blockIdx.x * blockDim.x + threadIdx.x) >> 5;
    int lane = threadIdx.x & 31;
    if (w >= BATCH * SEQ) return;
    int b = w / SEQ, s = w % SEQ;
    if (s < N_SOFT) return;

    long long idx = ldidx(x, (long long)b * SEQ + s, g_x64);
    if (idx < V_SIZE || idx >= V_SIZE + N_NODES) return;

    int slot = g_slot[idx - V_SIZE];
    const float4* s4 = (const float4*)(g_ne + (long long)slot * HDIM);
    float4* o4 = (float4*)(out + (long long)w * HDIM);
    #pragma unroll
    for (int j = 0; j < HDIM / 128; j++)
        o4[lane + 32 * j] = s4[lane + 32 * j];
}

// ---------------- launch ----------------
extern "C" void kernel_launch(void* const* d_in, const int* in_sizes, int n_in,
                              void* d_out, int out_size) {
    const void*  x    = d_in[0];
    const void*  ei   = d_in[1];
    const float* ow   = (const float*)d_in[2];
    const float* nw   = (const float*)d_in[3];
    const float* soft = (const float*)d_in[4];
    const float* Wg   = (const float*)d_in[5];
    const float* asrc = (const float*)d_in[6];
    const float* adst = (const float*)d_in[7];
    float* out = (float*)d_out;

    static cudaStream_t s_csr = nullptr, s_emb = nullptr, s_wv = nullptr;
    static cudaEvent_t  e_init = nullptr, e_csr = nullptr, e_emb = nullptr, e_sd = nullptr;
    if (!s_csr) {
        cudaFuncSetAttribute(k_gemm, cudaFuncAttributeMaxDynamicSharedMemorySize,
                             GEMM_SMEM_BYTES);
        cudaStreamCreateWithFlags(&s_csr, cudaStreamNonBlocking);
        cudaStreamCreateWithFlags(&s_emb, cudaStreamNonBlocking);
        cudaStreamCreateWithFlags(&s_wv,  cudaStreamNonBlocking);
        cudaEventCreateWithFlags(&e_init, cudaEventDisableTiming);
        cudaEventCreateWithFlags(&e_csr,  cudaEventDisableTiming);
        cudaEventCreateWithFlags(&e_emb,  cudaEventDisableTiming);
        cudaEventCreateWithFlags(&e_sd,   cudaEventDisableTiming);
    }

    // main stream: init (zero + dtype detect)
    k_init<<<(N_NODES + 1023) / 1024, 1024>>>((const unsigned*)x, (const unsigned*)ei);
    cudaEventRecord(e_init, 0);

    // s_wv: fork from capture-origin stream via event, then score chain
    cudaStreamWaitEvent(s_wv, e_init, 0);
    k_wvec<<<(HDIM * 32 + 255) / 256, 256, 0, s_wv>>>(Wg, asrc, adst);
    k_sdots<<<(N_NODES * 32 + 255) / 256, 256, 0, s_wv>>>(nw);
    cudaEventRecord(e_sd, s_wv);

    // s_csr: single bucket-scatter kernel
    cudaStreamWaitEvent(s_csr, e_init, 0);
    k_escatter<<<(N_EDGES + 1023) / 1024, 1024, 0, s_csr>>>(ei);
    cudaEventRecord(e_csr, s_csr);

    // s_emb: static gather
    cudaStreamWaitEvent(s_emb, e_init, 0);
    k_gather_static<<<(BATCH * SEQ * 32 + 255) / 256, 256, 0, s_emb>>>(x, ow, nw, soft, out);
    cudaEventRecord(e_emb, s_emb);

    // main stream: atomic flag + slot assignment (replaces flags + cscan)
    k_flagslot<<<(BATCH * SEQ + 255) / 256, 256>>>(x);

    // join bucket scatter + sdots, run feat-space GAT aggregation
    cudaStreamWaitEvent(0, e_csr, 0);
    cudaStreamWaitEvent(0, e_sd, 0);
    k_gat<<<(N_NODES * 32 + 255) / 256, 256>>>(nw);

    // compacted GEMM (agg @ W + feat)
    dim3 ggrid((N_NODES + BM - 1) / BM, HDIM / BN);
    k_gemm<<<ggrid, 256, GEMM_SMEM_BYTES>>>(Wg, nw);

    // dynamic gather
    cudaStreamWaitEvent(0, e_emb, 0);
    k_gather_dyn<<<(BATCH * SEQ * 32 + 255) / 256, 256>>>(x, out);
}